// round 4
// baseline (speedup 1.0000x reference)
#include <cuda_runtime.h>

// Problem constants
#define B_   32
#define C_   512
#define HW_  1024
#define R_   256

// Tiling
#define BM 128
#define BN 128
#define BK 16
#define TM 8
#define TN 8
#define NT 256

// Scratch: proj = [b][o(1024: 0-255 key, 256-511 prod, 512-1023 value)][hw]
// energy = [b][n][m] (later overwritten in-place with softmax)
__device__ float g_proj[33554432];    // 32*1024*1024 = 128 MB
__device__ float g_energy[33554432];  // 32*1024*1024 = 128 MB

// ---------------------------------------------------------------------------
// K1: stacked projection GEMM.  out[o,m] = sum_c W[o,c] * x[b,c,m] + bias[o]
// A = W  [M=o][K=c]  (transpose load, padded smem); B = x [K=c][N=m] (float4)
// Register-prefetch pipelined: tile k+1 loads overlap tile-k compute.
// ---------------------------------------------------------------------------
__global__ __launch_bounds__(NT) void k_proj(
    const float* __restrict__ x,
    const float* __restrict__ Wk, const float* __restrict__ bk,
    const float* __restrict__ Wp, const float* __restrict__ bp,
    const float* __restrict__ Wv, const float* __restrict__ bv)
{
    const int b     = blockIdx.z;
    const int oBase = blockIdx.y * BM;
    const int nBase = blockIdx.x * BN;

    // 128-row tile lies entirely in one segment (boundaries at 256, 512)
    const float* Wsel; const float* bsel; int oOff;
    if (oBase < R_)          { Wsel = Wk; bsel = bk; oOff = oBase; }
    else if (oBase < 2*R_)   { Wsel = Wp; bsel = bp; oOff = oBase - R_; }
    else                     { Wsel = Wv; bsel = bv; oOff = oBase - 2*R_; }

    __shared__ float As[BK][BM + 4];
    __shared__ float Bs[BK][BN];

    const int tid = threadIdx.x;
    const int tx  = tid & 15;
    const int ty  = tid >> 4;

    float acc[TM][TN];
    #pragma unroll
    for (int i = 0; i < TM; ++i)
        #pragma unroll
        for (int j = 0; j < TN; ++j) acc[i][j] = 0.f;

    const float* xb = x + (size_t)b * C_ * HW_;

    // Prologue: load tile k0=0 into registers
    float  aw[8];
    float4 bx[2];
    #pragma unroll
    for (int i = 0; i < 8; ++i) {
        int e = tid + i * NT;
        aw[i] = Wsel[(size_t)(oOff + (e >> 4)) * C_ + (e & 15)];
    }
    #pragma unroll
    for (int i = 0; i < 2; ++i) {
        int f = tid + i * NT;
        bx[i] = *(const float4*)(xb + (size_t)(f >> 5) * HW_ + nBase + ((f & 31) << 2));
    }

    for (int k0 = 0; k0 < C_; k0 += BK) {
        // Commit prefetched tile to smem
        #pragma unroll
        for (int i = 0; i < 8; ++i) {
            int e = tid + i * NT;
            As[e & 15][e >> 4] = aw[i];
        }
        #pragma unroll
        for (int i = 0; i < 2; ++i) {
            int f = tid + i * NT;
            *(float4*)&Bs[f >> 5][(f & 31) << 2] = bx[i];
        }
        __syncthreads();

        // Prefetch next tile into registers (overlaps compute below)
        const int kn = k0 + BK;
        if (kn < C_) {
            #pragma unroll
            for (int i = 0; i < 8; ++i) {
                int e = tid + i * NT;
                aw[i] = Wsel[(size_t)(oOff + (e >> 4)) * C_ + kn + (e & 15)];
            }
            #pragma unroll
            for (int i = 0; i < 2; ++i) {
                int f = tid + i * NT;
                bx[i] = *(const float4*)(xb + (size_t)(kn + (f >> 5)) * HW_ + nBase + ((f & 31) << 2));
            }
        }

        #pragma unroll
        for (int k = 0; k < BK; ++k) {
            float a[TM], bb[TN];
            *(float4*)&a[0]  = *(const float4*)&As[k][ty * TM];
            *(float4*)&a[4]  = *(const float4*)&As[k][ty * TM + 4];
            *(float4*)&bb[0] = *(const float4*)&Bs[k][tx * TN];
            *(float4*)&bb[4] = *(const float4*)&Bs[k][tx * TN + 4];
            #pragma unroll
            for (int i = 0; i < TM; ++i)
                #pragma unroll
                for (int j = 0; j < TN; ++j)
                    acc[i][j] = fmaf(a[i], bb[j], acc[i][j]);
        }
        __syncthreads();
    }

    float* outb = g_proj + (size_t)b * 1024 * HW_;
    #pragma unroll
    for (int i = 0; i < TM; ++i) {
        int o = oBase + ty * TM + i;
        float bias = bsel[oOff + ty * TM + i];
        float* orow = outb + (size_t)o * HW_ + nBase + tx * TN;
        float4 r0 = make_float4(acc[i][0] + bias, acc[i][1] + bias,
                                acc[i][2] + bias, acc[i][3] + bias);
        float4 r1 = make_float4(acc[i][4] + bias, acc[i][5] + bias,
                                acc[i][6] + bias, acc[i][7] + bias);
        *(float4*)&orow[0] = r0;
        *(float4*)&orow[4] = r1;
    }
}

// ---------------------------------------------------------------------------
// K2: energy[n,m] = sum_r key[r,n] * prod[r,m]
// Both operands K-major with contiguous output dim -> direct vector loads.
// Register-prefetch pipelined.
// ---------------------------------------------------------------------------
__global__ __launch_bounds__(NT) void k_energy()
{
    const int b     = blockIdx.z;
    const int nBase = blockIdx.y * BM;   // output row n
    const int mBase = blockIdx.x * BN;   // output col m

    const float* keyb  = g_proj + (size_t)b * 1024 * HW_;
    const float* prodb = keyb + (size_t)R_ * HW_;

    __shared__ float As[BK][BM];
    __shared__ float Bs[BK][BN];

    const int tid = threadIdx.x;
    const int tx  = tid & 15;
    const int ty  = tid >> 4;

    float acc[TM][TN];
    #pragma unroll
    for (int i = 0; i < TM; ++i)
        #pragma unroll
        for (int j = 0; j < TN; ++j) acc[i][j] = 0.f;

    // Prologue: tile k0=0
    float4 av[2], bv2[2];
    #pragma unroll
    for (int i = 0; i < 2; ++i) {
        int f  = tid + i * NT;
        int k  = f >> 5;
        int n4 = (f & 31) << 2;
        av[i]  = *(const float4*)(keyb  + (size_t)k * HW_ + nBase + n4);
        bv2[i] = *(const float4*)(prodb + (size_t)k * HW_ + mBase + n4);
    }

    for (int k0 = 0; k0 < R_; k0 += BK) {
        #pragma unroll
        for (int i = 0; i < 2; ++i) {
            int f  = tid + i * NT;
            int k  = f >> 5;
            int n4 = (f & 31) << 2;
            *(float4*)&As[k][n4] = av[i];
            *(float4*)&Bs[k][n4] = bv2[i];
        }
        __syncthreads();

        const int kn = k0 + BK;
        if (kn < R_) {
            #pragma unroll
            for (int i = 0; i < 2; ++i) {
                int f  = tid + i * NT;
                int k  = f >> 5;
                int n4 = (f & 31) << 2;
                av[i]  = *(const float4*)(keyb  + (size_t)(kn + k) * HW_ + nBase + n4);
                bv2[i] = *(const float4*)(prodb + (size_t)(kn + k) * HW_ + mBase + n4);
            }
        }

        #pragma unroll
        for (int k = 0; k < BK; ++k) {
            float a[TM], bb[TN];
            *(float4*)&a[0]  = *(const float4*)&As[k][ty * TM];
            *(float4*)&a[4]  = *(const float4*)&As[k][ty * TM + 4];
            *(float4*)&bb[0] = *(const float4*)&Bs[k][tx * TN];
            *(float4*)&bb[4] = *(const float4*)&Bs[k][tx * TN + 4];
            #pragma unroll
            for (int i = 0; i < TM; ++i)
                #pragma unroll
                for (int j = 0; j < TN; ++j)
                    acc[i][j] = fmaf(a[i], bb[j], acc[i][j]);
        }
        __syncthreads();
    }

    float* eb = g_energy + (size_t)b * HW_ * HW_;
    #pragma unroll
    for (int i = 0; i < TM; ++i) {
        int n = nBase + ty * TM + i;
        float* erow = eb + (size_t)n * HW_ + mBase + tx * TN;
        *(float4*)&erow[0] = make_float4(acc[i][0], acc[i][1], acc[i][2], acc[i][3]);
        *(float4*)&erow[4] = make_float4(acc[i][4], acc[i][5], acc[i][6], acc[i][7]);
    }
}

// ---------------------------------------------------------------------------
// K3: in-place row softmax over energy rows (length 1024), one block per row
// ---------------------------------------------------------------------------
__global__ __launch_bounds__(NT) void k_softmax()
{
    const size_t row = blockIdx.x;           // b*1024 + n
    float* p = g_energy + row * HW_;
    const int tid  = threadIdx.x;
    const int lane = tid & 31;
    const int wid  = tid >> 5;

    __shared__ float redmax[8];
    __shared__ float redsum[8];

    float v[4];
    #pragma unroll
    for (int i = 0; i < 4; ++i) v[i] = p[tid + i * NT];

    float m = fmaxf(fmaxf(v[0], v[1]), fmaxf(v[2], v[3]));
    #pragma unroll
    for (int o = 16; o > 0; o >>= 1)
        m = fmaxf(m, __shfl_xor_sync(0xFFFFFFFFu, m, o));
    if (lane == 0) redmax[wid] = m;
    __syncthreads();
    m = redmax[0];
    #pragma unroll
    for (int i = 1; i < 8; ++i) m = fmaxf(m, redmax[i]);

    float s = 0.f;
    #pragma unroll
    for (int i = 0; i < 4; ++i) { v[i] = expf(v[i] - m); s += v[i]; }
    #pragma unroll
    for (int o = 16; o > 0; o >>= 1)
        s += __shfl_xor_sync(0xFFFFFFFFu, s, o);
    if (lane == 0) redsum[wid] = s;
    __syncthreads();
    s = 0.f;
    #pragma unroll
    for (int i = 0; i < 8; ++i) s += redsum[i];
    float inv = 1.f / s;

    #pragma unroll
    for (int i = 0; i < 4; ++i) p[tid + i * NT] = v[i] * inv;
}

// ---------------------------------------------------------------------------
// K4: out[c,n] = x[c,n] + param * sum_m value[c,m] * sim[n,m]
// A = value [M=c][K=m], B = sim [N=n][K=m]  -> both transpose loads (NT GEMM)
// Register-prefetch pipelined.
// ---------------------------------------------------------------------------
__global__ __launch_bounds__(NT) void k_out(
    const float* __restrict__ x,
    const float* __restrict__ param,
    float* __restrict__ out)
{
    const int b     = blockIdx.z;
    const int cBase = blockIdx.y * BM;   // M = C (512)
    const int nBase = blockIdx.x * BN;   // N = HW (1024)

    const float* valb = g_proj + (size_t)b * 1024 * HW_ + (size_t)(2 * R_) * HW_;
    const float* simb = g_energy + (size_t)b * HW_ * HW_;

    __shared__ float As[BK][BM + 4];
    __shared__ float Bs[BK][BN + 4];

    const int tid = threadIdx.x;
    const int tx  = tid & 15;
    const int ty  = tid >> 4;

    float acc[TM][TN];
    #pragma unroll
    for (int i = 0; i < TM; ++i)
        #pragma unroll
        for (int j = 0; j < TN; ++j) acc[i][j] = 0.f;

    // Prologue: tile k0=0
    float avr[8], bvr[8];
    #pragma unroll
    for (int i = 0; i < 8; ++i) {
        int e = tid + i * NT;
        int m = e >> 4;
        int k = e & 15;
        avr[i] = valb[(size_t)(cBase + m) * HW_ + k];
        bvr[i] = simb[(size_t)(nBase + m) * HW_ + k];
    }

    for (int k0 = 0; k0 < HW_; k0 += BK) {
        #pragma unroll
        for (int i = 0; i < 8; ++i) {
            int e = tid + i * NT;
            int m = e >> 4;
            int k = e & 15;
            As[k][m] = avr[i];
            Bs[k][m] = bvr[i];
        }
        __syncthreads();

        const int kn = k0 + BK;
        if (kn < HW_) {
            #pragma unroll
            for (int i = 0; i < 8; ++i) {
                int e = tid + i * NT;
                int m = e >> 4;
                int k = e & 15;
                avr[i] = valb[(size_t)(cBase + m) * HW_ + kn + k];
                bvr[i] = simb[(size_t)(nBase + m) * HW_ + kn + k];
            }
        }

        #pragma unroll
        for (int k = 0; k < BK; ++k) {
            float a[TM], bb[TN];
            *(float4*)&a[0]  = *(const float4*)&As[k][ty * TM];
            *(float4*)&a[4]  = *(const float4*)&As[k][ty * TM + 4];
            *(float4*)&bb[0] = *(const float4*)&Bs[k][tx * TN];
            *(float4*)&bb[4] = *(const float4*)&Bs[k][tx * TN + 4];
            #pragma unroll
            for (int i = 0; i < TM; ++i)
                #pragma unroll
                for (int j = 0; j < TN; ++j)
                    acc[i][j] = fmaf(a[i], bb[j], acc[i][j]);
        }
        __syncthreads();
    }

    const float pscale = param[0];
    const float* xb = x   + (size_t)b * C_ * HW_;
    float*       ob = out + (size_t)b * C_ * HW_;
    #pragma unroll
    for (int i = 0; i < TM; ++i) {
        int c = cBase + ty * TM + i;
        size_t off = (size_t)c * HW_ + nBase + tx * TN;
        float4 x0 = *(const float4*)&xb[off];
        float4 x1 = *(const float4*)&xb[off + 4];
        float4 r0 = make_float4(x0.x + pscale * acc[i][0],
                                x0.y + pscale * acc[i][1],
                                x0.z + pscale * acc[i][2],
                                x0.w + pscale * acc[i][3]);
        float4 r1 = make_float4(x1.x + pscale * acc[i][4],
                                x1.y + pscale * acc[i][5],
                                x1.z + pscale * acc[i][6],
                                x1.w + pscale * acc[i][7]);
        *(float4*)&ob[off]     = r0;
        *(float4*)&ob[off + 4] = r1;
    }
}

// ---------------------------------------------------------------------------
// Launch
// ---------------------------------------------------------------------------
extern "C" void kernel_launch(void* const* d_in, const int* in_sizes, int n_in,
                              void* d_out, int out_size)
{
    const float* x     = (const float*)d_in[0];
    const float* Wk    = (const float*)d_in[1];
    const float* bk    = (const float*)d_in[2];
    const float* Wp    = (const float*)d_in[3];
    const float* bp    = (const float*)d_in[4];
    const float* Wv    = (const float*)d_in[5];
    const float* bv    = (const float*)d_in[6];
    const float* param = (const float*)d_in[7];
    float* out = (float*)d_out;

    dim3 block(NT);

    // K1: projections -> g_proj   (M=1024 o, N=1024 px, per batch)
    dim3 g1(HW_ / BN, 1024 / BM, B_);
    k_proj<<<g1, block>>>(x, Wk, bk, Wp, bp, Wv, bv);

    // K2: energy -> g_energy      (M=1024 n, N=1024 m, per batch)
    dim3 g2(HW_ / BN, HW_ / BM, B_);
    k_energy<<<g2, block>>>();

    // K3: in-place softmax over rows
    k_softmax<<<B_ * HW_, block>>>();

    // K4: attended + residual -> out  (M=512 c, N=1024 n, per batch)
    dim3 g4(HW_ / BN, C_ / BM, B_);
    k_out<<<g4, block>>>(x, param, out);
}

// round 11
// speedup vs baseline: 2.2677x; 2.2677x over previous
#include <cuda_runtime.h>
#include <cuda_bf16.h>
#include <cstdint>

// Problem constants
#define B_   32
#define C_   512
#define HW_  1024
#define R_   256

#define STRIDE 40   // bf16 elems per smem tile row (32 data + 8 pad, 80B, 16B-aligned)

// ---------------------------------------------------------------------------
// Scratch (fp32 intermediates)
// ---------------------------------------------------------------------------
__device__ float g_xT[16777216];      // [B][HW][C]   x transposed
__device__ float g_projT[16777216];   // [B][HW][512] key(0:256)+prod(256:512)
__device__ float g_val[16777216];     // [B][512][HW] value projection
__device__ float g_energy[33554432];  // [B][HW][HW]  energy -> softmax in place

// ---------------------------------------------------------------------------
// Helpers
// ---------------------------------------------------------------------------
__device__ __forceinline__ uint32_t s2u(const void* p) {
    uint32_t a;
    asm("{ .reg .u64 t; cvta.to.shared.u64 t, %1; cvt.u32.u64 %0, t; }"
        : "=r"(a) : "l"(p));
    return a;
}

// mma.sync m16n8k16 row.col f32.bf16.bf16.f32 (sm_80+, legal at base sm_103)
__device__ __forceinline__ void mma16816(float* d, const uint32_t* a, const uint32_t* b) {
    asm volatile(
        "mma.sync.aligned.m16n8k16.row.col.f32.bf16.bf16.f32 "
        "{%0,%1,%2,%3}, {%4,%5,%6,%7}, {%8,%9}, {%0,%1,%2,%3};"
        : "+f"(d[0]), "+f"(d[1]), "+f"(d[2]), "+f"(d[3])
        : "r"(a[0]), "r"(a[1]), "r"(a[2]), "r"(a[3]), "r"(b[0]), "r"(b[1]));
}

__device__ __forceinline__ void ldmx4(uint32_t* r, uint32_t addr) {
    asm volatile("ldmatrix.sync.aligned.m8n8.x4.shared.b16 {%0,%1,%2,%3}, [%4];"
                 : "=r"(r[0]), "=r"(r[1]), "=r"(r[2]), "=r"(r[3]) : "r"(addr));
}

// ---------------------------------------------------------------------------
// Fill one 128x32 fp32 tile -> hi/lo bf16 smem tiles [128][STRIDE].
// 256 threads: thread t -> row t>>1, 16-col half (t&1)*16.
// ---------------------------------------------------------------------------
__device__ __forceinline__ void fill_split32(const float* __restrict__ src, int stride,
                                             __nv_bfloat16* sh, __nv_bfloat16* sl, int tid) {
    const int row = tid >> 1;
    const int cb  = (tid & 1) << 4;
    const float* p = src + (size_t)row * stride + cb;
    __nv_bfloat16* ph = sh + row * STRIDE + cb;
    __nv_bfloat16* pl = sl + row * STRIDE + cb;
    #pragma unroll
    for (int i = 0; i < 4; ++i) {
        float4 v = *(const float4*)(p + i * 4);
        __nv_bfloat162 h01 = __floats2bfloat162_rn(v.x, v.y);
        __nv_bfloat162 h23 = __floats2bfloat162_rn(v.z, v.w);
        __nv_bfloat162 l01 = __floats2bfloat162_rn(v.x - __bfloat162float(h01.x),
                                                   v.y - __bfloat162float(h01.y));
        __nv_bfloat162 l23 = __floats2bfloat162_rn(v.z - __bfloat162float(h23.x),
                                                   v.w - __bfloat162float(h23.y));
        uint2 wh, wl;
        wh.x = reinterpret_cast<uint32_t&>(h01);
        wh.y = reinterpret_cast<uint32_t&>(h23);
        wl.x = reinterpret_cast<uint32_t&>(l01);
        wl.y = reinterpret_cast<uint32_t&>(l23);
        *(uint2*)(ph + i * 4) = wh;
        *(uint2*)(pl + i * 4) = wl;
    }
}

// ---------------------------------------------------------------------------
// GEMM core: D[128][128] = sum_k A[128][K] * B[128][K],  K = 32*nChunks.
// A rows = M dim, B rows = N dim, both K-contiguous in gmem.
// 8 warps: wm = wid&3 -> M quadrant (32 rows), wn = wid>>2 -> N half (64 cols).
// acc[i][j][4]: i = m16 tile (0,1), j = n8 tile (0..7).
// 3-product bf16 split: ah*bh + ah*bl + al*bh.
// ---------------------------------------------------------------------------
__device__ __forceinline__ void gemm_core(
    const float* __restrict__ aSrc, int aStride,
    const float* __restrict__ bSrc, int bStride,
    int nChunks,
    __nv_bfloat16* sAH, __nv_bfloat16* sAL,
    __nv_bfloat16* sBH, __nv_bfloat16* sBL,
    float acc[2][8][4]) {
    const int tid  = threadIdx.x;
    const int lane = tid & 31;
    const int wid  = tid >> 5;
    const int am   = (wid & 3) * 32;
    const int bn   = (wid >> 2) * 64;

    const uint32_t uAH = s2u(sAH), uAL = s2u(sAL);
    const uint32_t uBH = s2u(sBH), uBL = s2u(sBL);

    // lane -> ldmatrix source row/col (within warp tile), per x4 semantics:
    // A: mat mi=lane>>3: row = (lane&7) + (mi&1)*8, col = (mi>>1)*8
    const int aro = (lane & 7) + ((lane >> 3) & 1) * 8;
    const int aco = ((lane >> 4) & 1) * 8;
    // B: mat mi: n = (mi>>1)*8 + (lane&7), k = (mi&1)*8
    const int bro = ((lane >> 4) << 3) + (lane & 7);
    const int bco = ((lane >> 3) & 1) * 8;

    for (int ch = 0; ch < nChunks; ++ch) {
        fill_split32(aSrc + ch * 32, aStride, sAH, sAL, tid);
        fill_split32(bSrc + ch * 32, bStride, sBH, sBL, tid);
        __syncthreads();
        #pragma unroll
        for (int ks = 0; ks < 2; ++ks) {
            const int k0 = ks * 16;
            const uint32_t aoff = (uint32_t)((am + aro) * STRIDE + k0 + aco) * 2;
            uint32_t ah[2][4], al[2][4];
            ldmx4(ah[0], uAH + aoff);
            ldmx4(ah[1], uAH + aoff + 16 * STRIDE * 2);
            ldmx4(al[0], uAL + aoff);
            ldmx4(al[1], uAL + aoff + 16 * STRIDE * 2);

            const uint32_t boff = (uint32_t)((bn + bro) * STRIDE + k0 + bco) * 2;
            uint32_t bh[8][2], bl[8][2];
            #pragma unroll
            for (int g = 0; g < 4; ++g) {           // each x4 covers 2 n8-tiles
                uint32_t r[4];
                ldmx4(r, uBH + boff + g * 16 * STRIDE * 2);
                bh[g*2][0] = r[0]; bh[g*2][1] = r[1];
                bh[g*2+1][0] = r[2]; bh[g*2+1][1] = r[3];
                ldmx4(r, uBL + boff + g * 16 * STRIDE * 2);
                bl[g*2][0] = r[0]; bl[g*2][1] = r[1];
                bl[g*2+1][0] = r[2]; bl[g*2+1][1] = r[3];
            }
            #pragma unroll
            for (int i = 0; i < 2; ++i)
                #pragma unroll
                for (int j = 0; j < 8; ++j) {
                    mma16816(acc[i][j], ah[i], bh[j]);
                    mma16816(acc[i][j], ah[i], bl[j]);
                    mma16816(acc[i][j], al[i], bh[j]);
                }
        }
        __syncthreads();
    }
}

#define DECL_TILES()                                                   \
    __shared__ __align__(16) __nv_bfloat16 sAH[128 * STRIDE];          \
    __shared__ __align__(16) __nv_bfloat16 sAL[128 * STRIDE];          \
    __shared__ __align__(16) __nv_bfloat16 sBH[128 * STRIDE];          \
    __shared__ __align__(16) __nv_bfloat16 sBL[128 * STRIDE];          \
    float acc[2][8][4];                                                \
    _Pragma("unroll") for (int i = 0; i < 2; ++i)                      \
        _Pragma("unroll") for (int j = 0; j < 8; ++j)                  \
            _Pragma("unroll") for (int q = 0; q < 4; ++q)              \
                acc[i][j][q] = 0.f;

// Epilogue index helpers: M row, N col for (i, j, lane)
#define EPI_M(i)  (((threadIdx.x >> 5) & 3) * 32 + (i) * 16 + ((threadIdx.x & 31) >> 2))
#define EPI_N(j)  (((threadIdx.x >> 5) >> 2) * 64 + (j) * 8 + ((threadIdx.x & 3) << 1))

// ---------------------------------------------------------------------------
// K0: transpose x[b][c][m] -> xT[b][m][c]
// ---------------------------------------------------------------------------
__global__ __launch_bounds__(256) void k_transpose(const float* __restrict__ x) {
    __shared__ float t[32][33];
    const int b = blockIdx.z;
    const int mB = blockIdx.x * 32, cB = blockIdx.y * 32;
    const int tx = threadIdx.x & 31, ty = threadIdx.x >> 5;
    const float* xb = x + ((size_t)b * C_ + cB) * HW_ + mB;
    #pragma unroll
    for (int j = 0; j < 32; j += 8)
        t[ty + j][tx] = xb[(size_t)(ty + j) * HW_ + tx];
    __syncthreads();
    float* o = g_xT + ((size_t)b * HW_ + mB) * C_ + cB;
    #pragma unroll
    for (int j = 0; j < 32; j += 8)
        o[(size_t)(ty + j) * C_ + tx] = t[tx][ty + j];
}

// ---------------------------------------------------------------------------
// K1a: projT[b][m][o] = sum_c xT[m,c]*W[o,c] + bias[o]     (M=m, N=o, K=512)
// ---------------------------------------------------------------------------
__global__ __launch_bounds__(256) void k_proj_kp(
    const float* __restrict__ Wk, const float* __restrict__ bk,
    const float* __restrict__ Wp, const float* __restrict__ bp) {
    const int b = blockIdx.z, oBase = blockIdx.x * 128, mBase = blockIdx.y * 128;
    DECL_TILES();
    const float* aSrc = g_xT + ((size_t)b * HW_ + mBase) * C_;
    const float* bSrc = (oBase < R_) ? (Wk + (size_t)oBase * C_)
                                     : (Wp + (size_t)(oBase - R_) * C_);
    gemm_core(aSrc, C_, bSrc, C_, 16, sAH, sAL, sBH, sBL, acc);

    const float* bias = (oBase < R_) ? (bk + oBase) : (bp + oBase - R_);
    #pragma unroll
    for (int i = 0; i < 2; ++i)
        #pragma unroll
        for (int j = 0; j < 8; ++j) {
            const int m0 = mBase + EPI_M(i);
            const int lc = EPI_N(j);
            const float b0 = bias[lc], b1 = bias[lc + 1];
            float* d0 = g_projT + ((size_t)b * HW_ + m0) * 512 + oBase + lc;
            float* d1 = g_projT + ((size_t)b * HW_ + m0 + 8) * 512 + oBase + lc;
            *(float2*)d0 = make_float2(acc[i][j][0] + b0, acc[i][j][1] + b1);
            *(float2*)d1 = make_float2(acc[i][j][2] + b0, acc[i][j][3] + b1);
        }
}

// ---------------------------------------------------------------------------
// K1b: val[b][c][m] = sum_cin Wv[c,cin]*xT[m,cin] + bv[c]  (M=c, N=m, K=512)
// ---------------------------------------------------------------------------
__global__ __launch_bounds__(256) void k_proj_v(
    const float* __restrict__ Wv, const float* __restrict__ bv) {
    const int b = blockIdx.z, mBase = blockIdx.x * 128, cBase = blockIdx.y * 128;
    DECL_TILES();
    const float* aSrc = Wv + (size_t)cBase * C_;
    const float* bSrc = g_xT + ((size_t)b * HW_ + mBase) * C_;
    gemm_core(aSrc, C_, bSrc, C_, 16, sAH, sAL, sBH, sBL, acc);

    #pragma unroll
    for (int i = 0; i < 2; ++i)
        #pragma unroll
        for (int j = 0; j < 8; ++j) {
            const int c0 = cBase + EPI_M(i);
            const int lm = EPI_N(j);
            const float b0 = bv[c0], b1 = bv[c0 + 8];
            float* d0 = g_val + ((size_t)b * C_ + c0) * HW_ + mBase + lm;
            float* d1 = g_val + ((size_t)b * C_ + c0 + 8) * HW_ + mBase + lm;
            *(float2*)d0 = make_float2(acc[i][j][0] + b0, acc[i][j][1] + b0);
            *(float2*)d1 = make_float2(acc[i][j][2] + b1, acc[i][j][3] + b1);
        }
}

// ---------------------------------------------------------------------------
// K2: energy[b][n][m] = sum_r projT[n][r]*projT[m][256+r]  (M=n, N=m, K=256)
// ---------------------------------------------------------------------------
__global__ __launch_bounds__(256) void k_energy_t() {
    const int b = blockIdx.z, mBase = blockIdx.x * 128, nBase = blockIdx.y * 128;
    DECL_TILES();
    const float* aSrc = g_projT + ((size_t)b * HW_ + nBase) * 512;        // key
    const float* bSrc = g_projT + ((size_t)b * HW_ + mBase) * 512 + R_;   // prod
    gemm_core(aSrc, 512, bSrc, 512, 8, sAH, sAL, sBH, sBL, acc);

    #pragma unroll
    for (int i = 0; i < 2; ++i)
        #pragma unroll
        for (int j = 0; j < 8; ++j) {
            const int n0 = nBase + EPI_M(i);
            const int lm = EPI_N(j);
            float* d0 = g_energy + ((size_t)b * HW_ + n0) * HW_ + mBase + lm;
            float* d1 = g_energy + ((size_t)b * HW_ + n0 + 8) * HW_ + mBase + lm;
            *(float2*)d0 = make_float2(acc[i][j][0], acc[i][j][1]);
            *(float2*)d1 = make_float2(acc[i][j][2], acc[i][j][3]);
        }
}

// ---------------------------------------------------------------------------
// K3: in-place row softmax over energy rows (length 1024)
// ---------------------------------------------------------------------------
__global__ __launch_bounds__(256) void k_softmax() {
    const size_t row = blockIdx.x;
    float* p = g_energy + row * HW_;
    const int tid = threadIdx.x, lane = tid & 31, wid = tid >> 5;
    __shared__ float redmax[8], redsum[8];

    float v[4];
    #pragma unroll
    for (int i = 0; i < 4; ++i) v[i] = p[tid + i * 256];

    float m = fmaxf(fmaxf(v[0], v[1]), fmaxf(v[2], v[3]));
    #pragma unroll
    for (int o = 16; o > 0; o >>= 1)
        m = fmaxf(m, __shfl_xor_sync(0xFFFFFFFFu, m, o));
    if (lane == 0) redmax[wid] = m;
    __syncthreads();
    m = redmax[0];
    #pragma unroll
    for (int i = 1; i < 8; ++i) m = fmaxf(m, redmax[i]);

    float s = 0.f;
    #pragma unroll
    for (int i = 0; i < 4; ++i) { v[i] = expf(v[i] - m); s += v[i]; }
    #pragma unroll
    for (int o = 16; o > 0; o >>= 1)
        s += __shfl_xor_sync(0xFFFFFFFFu, s, o);
    if (lane == 0) redsum[wid] = s;
    __syncthreads();
    s = 0.f;
    #pragma unroll
    for (int i = 0; i < 8; ++i) s += redsum[i];
    const float inv = 1.f / s;
    #pragma unroll
    for (int i = 0; i < 4; ++i) p[tid + i * 256] = v[i] * inv;
}

// ---------------------------------------------------------------------------
// K4: out[b][c][n] = x[b][c][n] + param*sum_m val[c][m]*sim[n][m] (M=c,N=n,K=1024)
// ---------------------------------------------------------------------------
__global__ __launch_bounds__(256) void k_attn_out(
    const float* __restrict__ x, const float* __restrict__ param,
    float* __restrict__ out) {
    const int b = blockIdx.z, nBase = blockIdx.x * 128, cBase = blockIdx.y * 128;
    DECL_TILES();
    const float* aSrc = g_val + ((size_t)b * C_ + cBase) * HW_;
    const float* bSrc = g_energy + ((size_t)b * HW_ + nBase) * HW_;  // softmaxed
    gemm_core(aSrc, HW_, bSrc, HW_, 32, sAH, sAL, sBH, sBL, acc);

    const float ps = param[0];
    #pragma unroll
    for (int i = 0; i < 2; ++i)
        #pragma unroll
        for (int j = 0; j < 8; ++j) {
            const int c0 = cBase + EPI_M(i);
            const int ln = EPI_N(j);
            const size_t o0 = ((size_t)b * C_ + c0) * HW_ + nBase + ln;
            const size_t o1 = ((size_t)b * C_ + c0 + 8) * HW_ + nBase + ln;
            float2 x0 = *(const float2*)(x + o0);
            float2 x1 = *(const float2*)(x + o1);
            *(float2*)(out + o0) = make_float2(x0.x + ps * acc[i][j][0],
                                               x0.y + ps * acc[i][j][1]);
            *(float2*)(out + o1) = make_float2(x1.x + ps * acc[i][j][2],
                                               x1.y + ps * acc[i][j][3]);
        }
}

// ---------------------------------------------------------------------------
// Launch
// ---------------------------------------------------------------------------
extern "C" void kernel_launch(void* const* d_in, const int* in_sizes, int n_in,
                              void* d_out, int out_size) {
    const float* x     = (const float*)d_in[0];
    const float* Wk    = (const float*)d_in[1];
    const float* bk    = (const float*)d_in[2];
    const float* Wp    = (const float*)d_in[3];
    const float* bp    = (const float*)d_in[4];
    const float* Wv    = (const float*)d_in[5];
    const float* bv    = (const float*)d_in[6];
    const float* param = (const float*)d_in[7];
    float* out = (float*)d_out;

    // K0: x -> xT
    k_transpose<<<dim3(HW_ / 32, C_ / 32, B_), 256>>>(x);

    // K1a: key+prod projections -> projT
    k_proj_kp<<<dim3(4, 8, B_), 256>>>(Wk, bk, Wp, bp);

    // K1b: value projection -> val
    k_proj_v<<<dim3(8, 4, B_), 256>>>(Wv, bv);

    // K2: energy
    k_energy_t<<<dim3(8, 8, B_), 256>>>();

    // K3: softmax in place
    k_softmax<<<B_ * HW_, 256>>>();

    // K4: attended + residual -> out
    k_attn_out<<<dim3(8, 4, B_), 256>>>(x, param, out);
}

// round 15
// speedup vs baseline: 2.7971x; 1.2335x over previous
#include <cuda_runtime.h>
#include <cuda_bf16.h>
#include <cstdint>

// Problem constants
#define B_   32
#define C_   512
#define HW_  1024
#define R_   256

#define STRIDE 40          // bf16 per smem tile row (32 data + 8 pad; conflict-free ldmatrix)
#define TILE_E (128 * STRIDE)        // bf16 elems per tile (10240 B)
#define STAGE_E (4 * TILE_E)         // AH, AL, BH, BL per stage
#define SMEM_BYTES (2 * STAGE_E * 2) // 2 stages * bytes  = 81920

// ---------------------------------------------------------------------------
// Scratch (fp32 intermediates)
// ---------------------------------------------------------------------------
__device__ float g_xT[16777216];      // [B][HW][C]
__device__ float g_projT[16777216];   // [B][HW][512] key | prod
__device__ float g_val[16777216];     // [B][512][HW]
__device__ float g_energy[33554432];  // [B][HW][HW] energy -> softmax in place

// ---------------------------------------------------------------------------
// Helpers
// ---------------------------------------------------------------------------
__device__ __forceinline__ uint32_t s2u(const void* p) {
    uint32_t a;
    asm("{ .reg .u64 t; cvta.to.shared.u64 t, %1; cvt.u32.u64 %0, t; }"
        : "=r"(a) : "l"(p));
    return a;
}

__device__ __forceinline__ void mma16816(float* d, const uint32_t* a, const uint32_t* b) {
    asm volatile(
        "mma.sync.aligned.m16n8k16.row.col.f32.bf16.bf16.f32 "
        "{%0,%1,%2,%3}, {%4,%5,%6,%7}, {%8,%9}, {%0,%1,%2,%3};"
        : "+f"(d[0]), "+f"(d[1]), "+f"(d[2]), "+f"(d[3])
        : "r"(a[0]), "r"(a[1]), "r"(a[2]), "r"(a[3]), "r"(b[0]), "r"(b[1]));
}

__device__ __forceinline__ void ldmx4(uint32_t* r, uint32_t addr) {
    asm volatile("ldmatrix.sync.aligned.m8n8.x4.shared.b16 {%0,%1,%2,%3}, [%4];"
                 : "=r"(r[0]), "=r"(r[1]), "=r"(r[2]), "=r"(r[3]) : "r"(addr));
}

// ---------------------------------------------------------------------------
// Fill one 128x32 fp32 tile -> hi/lo bf16 tiles. 128 fill threads (ft 0..127):
// warp covers 4 rows x 8 float4 -> 128B-coalesced gmem rows.
// ---------------------------------------------------------------------------
__device__ __forceinline__ void fill_tile(const float* __restrict__ src, int stride,
                                          __nv_bfloat16* sh, __nv_bfloat16* sl, int ft) {
    const int rbase = ft >> 3;         // 0..15
    const int cq    = (ft & 7) * 4;    // float col 0,4,..,28
    #pragma unroll
    for (int rr = 0; rr < 8; ++rr) {
        const int row = rr * 16 + rbase;
        float4 v = *(const float4*)(src + (size_t)row * stride + cq);
        __nv_bfloat162 h01 = __floats2bfloat162_rn(v.x, v.y);
        __nv_bfloat162 h23 = __floats2bfloat162_rn(v.z, v.w);
        __nv_bfloat162 l01 = __floats2bfloat162_rn(v.x - __bfloat162float(h01.x),
                                                   v.y - __bfloat162float(h01.y));
        __nv_bfloat162 l23 = __floats2bfloat162_rn(v.z - __bfloat162float(h23.x),
                                                   v.w - __bfloat162float(h23.y));
        uint2 wh, wl;
        wh.x = reinterpret_cast<uint32_t&>(h01);
        wh.y = reinterpret_cast<uint32_t&>(h23);
        wl.x = reinterpret_cast<uint32_t&>(l01);
        wl.y = reinterpret_cast<uint32_t&>(l23);
        *(uint2*)(sh + row * STRIDE + cq) = wh;
        *(uint2*)(sl + row * STRIDE + cq) = wl;
    }
}

// ---------------------------------------------------------------------------
// GEMM core: D[128][128] = sum_k A[128][K]*B[128][K], K = 32*nChunks.
// 256 threads: warps 0-3 compute (64x64 tiles, 2x2 grid), warps 4-7 fill.
// 2-stage double buffer; 3-product bf16 split (ah*bh + ah*bl + al*bh).
// ---------------------------------------------------------------------------
__device__ __forceinline__ void gemm_core(
    const float* __restrict__ aSrc, int aStride,
    const float* __restrict__ bSrc, int bStride,
    int nChunks, __nv_bfloat16* dsm, float acc[4][8][4]) {
    const int tid  = threadIdx.x;
    const int lane = tid & 31;
    const int wid  = tid >> 5;

    // ldmatrix lane->addr maps (proven in R11 kernel)
    const int aro = (lane & 7) + ((lane >> 3) & 1) * 8;
    const int aco = ((lane >> 4) & 1) * 8;
    const int bro = ((lane >> 4) << 3) + (lane & 7);
    const int bco = ((lane >> 3) & 1) * 8;

    const int am = (wid & 1) * 64;          // compute warp M half
    const int bn = ((wid >> 1) & 1) * 64;   // compute warp N half
    const int ft = tid - 128;               // fill thread id (warps 4-7)

    const uint32_t base = s2u(dsm);

    // Prologue: fill warps stage chunk 0 into stage 0
    if (wid >= 4) {
        fill_tile(aSrc, aStride, dsm, dsm + TILE_E, ft);
        fill_tile(bSrc, bStride, dsm + 2 * TILE_E, dsm + 3 * TILE_E, ft);
    }
    __syncthreads();

    for (int ch = 0; ch < nChunks; ++ch) {
        const int s = ch & 1;
        if (wid >= 4) {
            if (ch + 1 < nChunks) {
                __nv_bfloat16* st = dsm + (s ^ 1) * STAGE_E;
                fill_tile(aSrc + (ch + 1) * 32, aStride, st, st + TILE_E, ft);
                fill_tile(bSrc + (ch + 1) * 32, bStride, st + 2 * TILE_E, st + 3 * TILE_E, ft);
            }
        } else {
            const uint32_t sb  = base + (uint32_t)s * (STAGE_E * 2);
            const uint32_t uAH = sb;
            const uint32_t uAL = sb + TILE_E * 2;
            const uint32_t uBH = sb + 2 * TILE_E * 2;
            const uint32_t uBL = sb + 3 * TILE_E * 2;
            #pragma unroll
            for (int ks = 0; ks < 2; ++ks) {
                const int k0 = ks * 16;
                const uint32_t aoff = (uint32_t)((am + aro) * STRIDE + k0 + aco) * 2;
                uint32_t ah[4][4], al[4][4];
                #pragma unroll
                for (int i = 0; i < 4; ++i) {
                    ldmx4(ah[i], uAH + aoff + i * (16 * STRIDE * 2));
                    ldmx4(al[i], uAL + aoff + i * (16 * STRIDE * 2));
                }
                const uint32_t boff = (uint32_t)((bn + bro) * STRIDE + k0 + bco) * 2;
                uint32_t bh[8][2], bl[8][2];
                #pragma unroll
                for (int g = 0; g < 4; ++g) {       // each x4 covers 2 n8-tiles
                    uint32_t r[4];
                    ldmx4(r, uBH + boff + g * (16 * STRIDE * 2));
                    bh[g*2][0] = r[0]; bh[g*2][1] = r[1];
                    bh[g*2+1][0] = r[2]; bh[g*2+1][1] = r[3];
                    ldmx4(r, uBL + boff + g * (16 * STRIDE * 2));
                    bl[g*2][0] = r[0]; bl[g*2][1] = r[1];
                    bl[g*2+1][0] = r[2]; bl[g*2+1][1] = r[3];
                }
                #pragma unroll
                for (int i = 0; i < 4; ++i)
                    #pragma unroll
                    for (int j = 0; j < 8; ++j) {
                        mma16816(acc[i][j], ah[i], bh[j]);
                        mma16816(acc[i][j], ah[i], bl[j]);
                        mma16816(acc[i][j], al[i], bh[j]);
                    }
            }
        }
        __syncthreads();
    }
}

#define DECL_ACC()                                                     \
    float acc[4][8][4];                                                \
    _Pragma("unroll") for (int i = 0; i < 4; ++i)                      \
        _Pragma("unroll") for (int j = 0; j < 8; ++j)                  \
            _Pragma("unroll") for (int q = 0; q < 4; ++q)              \
                acc[i][j][q] = 0.f;

// Epilogue mapping (compute warps only): 2x2 warp grid, 64x64 tiles
#define EPI_M(i)  (((threadIdx.x >> 5) & 1) * 64 + (i) * 16 + ((threadIdx.x & 31) >> 2))
#define EPI_N(j)  ((((threadIdx.x >> 5) >> 1) & 1) * 64 + (j) * 8 + ((threadIdx.x & 3) << 1))

// ---------------------------------------------------------------------------
// K0: transpose x[b][c][m] -> xT[b][m][c]
// ---------------------------------------------------------------------------
__global__ __launch_bounds__(256) void k_transpose(const float* __restrict__ x) {
    __shared__ float t[32][33];
    const int b = blockIdx.z;
    const int mB = blockIdx.x * 32, cB = blockIdx.y * 32;
    const int tx = threadIdx.x & 31, ty = threadIdx.x >> 5;
    const float* xb = x + ((size_t)b * C_ + cB) * HW_ + mB;
    #pragma unroll
    for (int j = 0; j < 32; j += 8)
        t[ty + j][tx] = xb[(size_t)(ty + j) * HW_ + tx];
    __syncthreads();
    float* o = g_xT + ((size_t)b * HW_ + mB) * C_ + cB;
    #pragma unroll
    for (int j = 0; j < 32; j += 8)
        o[(size_t)(ty + j) * C_ + tx] = t[tx][ty + j];
}

// ---------------------------------------------------------------------------
// K1a: projT[b][m][o] = sum_c xT[m,c]*W[o,c] + bias[o]   (M=m, N=o, K=512)
// ---------------------------------------------------------------------------
__global__ __launch_bounds__(256) void k_proj_kp(
    const float* __restrict__ Wk, const float* __restrict__ bk,
    const float* __restrict__ Wp, const float* __restrict__ bp) {
    extern __shared__ __align__(16) __nv_bfloat16 dsm[];
    const int b = blockIdx.z, oBase = blockIdx.x * 128, mBase = blockIdx.y * 128;
    DECL_ACC();
    const float* aSrc = g_xT + ((size_t)b * HW_ + mBase) * C_;
    const float* bSrc = (oBase < R_) ? (Wk + (size_t)oBase * C_)
                                     : (Wp + (size_t)(oBase - R_) * C_);
    gemm_core(aSrc, C_, bSrc, C_, 16, dsm, acc);

    if ((threadIdx.x >> 5) < 4) {
        const float* bias = (oBase < R_) ? (bk + oBase) : (bp + oBase - R_);
        #pragma unroll
        for (int i = 0; i < 4; ++i)
            #pragma unroll
            for (int j = 0; j < 8; ++j) {
                const int m0 = mBase + EPI_M(i);
                const int lc = EPI_N(j);
                const float b0 = bias[lc], b1 = bias[lc + 1];
                float* d0 = g_projT + ((size_t)b * HW_ + m0) * 512 + oBase + lc;
                float* d1 = g_projT + ((size_t)b * HW_ + m0 + 8) * 512 + oBase + lc;
                *(float2*)d0 = make_float2(acc[i][j][0] + b0, acc[i][j][1] + b1);
                *(float2*)d1 = make_float2(acc[i][j][2] + b0, acc[i][j][3] + b1);
            }
    }
}

// ---------------------------------------------------------------------------
// K1b: val[b][c][m] = sum_cin Wv[c,cin]*xT[m,cin] + bv[c] (M=c, N=m, K=512)
// ---------------------------------------------------------------------------
__global__ __launch_bounds__(256) void k_proj_v(
    const float* __restrict__ Wv, const float* __restrict__ bv) {
    extern __shared__ __align__(16) __nv_bfloat16 dsm[];
    const int b = blockIdx.z, mBase = blockIdx.x * 128, cBase = blockIdx.y * 128;
    DECL_ACC();
    const float* aSrc = Wv + (size_t)cBase * C_;
    const float* bSrc = g_xT + ((size_t)b * HW_ + mBase) * C_;
    gemm_core(aSrc, C_, bSrc, C_, 16, dsm, acc);

    if ((threadIdx.x >> 5) < 4) {
        #pragma unroll
        for (int i = 0; i < 4; ++i)
            #pragma unroll
            for (int j = 0; j < 8; ++j) {
                const int c0 = cBase + EPI_M(i);
                const int lm = EPI_N(j);
                const float b0 = bv[c0], b1 = bv[c0 + 8];
                float* d0 = g_val + ((size_t)b * C_ + c0) * HW_ + mBase + lm;
                float* d1 = g_val + ((size_t)b * C_ + c0 + 8) * HW_ + mBase + lm;
                *(float2*)d0 = make_float2(acc[i][j][0] + b0, acc[i][j][1] + b0);
                *(float2*)d1 = make_float2(acc[i][j][2] + b1, acc[i][j][3] + b1);
            }
    }
}

// ---------------------------------------------------------------------------
// K2: energy[b][n][m] = sum_r projT[n][r]*projT[m][256+r] (M=n, N=m, K=256)
// ---------------------------------------------------------------------------
__global__ __launch_bounds__(256) void k_energy_t() {
    extern __shared__ __align__(16) __nv_bfloat16 dsm[];
    const int b = blockIdx.z, mBase = blockIdx.x * 128, nBase = blockIdx.y * 128;
    DECL_ACC();
    const float* aSrc = g_projT + ((size_t)b * HW_ + nBase) * 512;        // key
    const float* bSrc = g_projT + ((size_t)b * HW_ + mBase) * 512 + R_;   // prod
    gemm_core(aSrc, 512, bSrc, 512, 8, dsm, acc);

    if ((threadIdx.x >> 5) < 4) {
        #pragma unroll
        for (int i = 0; i < 4; ++i)
            #pragma unroll
            for (int j = 0; j < 8; ++j) {
                const int n0 = nBase + EPI_M(i);
                const int lm = EPI_N(j);
                float* d0 = g_energy + ((size_t)b * HW_ + n0) * HW_ + mBase + lm;
                float* d1 = g_energy + ((size_t)b * HW_ + n0 + 8) * HW_ + mBase + lm;
                *(float2*)d0 = make_float2(acc[i][j][0], acc[i][j][1]);
                *(float2*)d1 = make_float2(acc[i][j][2], acc[i][j][3]);
            }
    }
}

// ---------------------------------------------------------------------------
// K3: in-place row softmax over energy rows (length 1024)
// ---------------------------------------------------------------------------
__global__ __launch_bounds__(256) void k_softmax() {
    const size_t row = blockIdx.x;
    float* p = g_energy + row * HW_;
    const int tid = threadIdx.x, lane = tid & 31, wid = tid >> 5;
    __shared__ float redmax[8], redsum[8];

    float v[4];
    #pragma unroll
    for (int i = 0; i < 4; ++i) v[i] = p[tid + i * 256];

    float m = fmaxf(fmaxf(v[0], v[1]), fmaxf(v[2], v[3]));
    #pragma unroll
    for (int o = 16; o > 0; o >>= 1)
        m = fmaxf(m, __shfl_xor_sync(0xFFFFFFFFu, m, o));
    if (lane == 0) redmax[wid] = m;
    __syncthreads();
    m = redmax[0];
    #pragma unroll
    for (int i = 1; i < 8; ++i) m = fmaxf(m, redmax[i]);

    float s = 0.f;
    #pragma unroll
    for (int i = 0; i < 4; ++i) { v[i] = expf(v[i] - m); s += v[i]; }
    #pragma unroll
    for (int o = 16; o > 0; o >>= 1)
        s += __shfl_xor_sync(0xFFFFFFFFu, s, o);
    if (lane == 0) redsum[wid] = s;
    __syncthreads();
    s = 0.f;
    #pragma unroll
    for (int i = 0; i < 8; ++i) s += redsum[i];
    const float inv = 1.f / s;
    #pragma unroll
    for (int i = 0; i < 4; ++i) p[tid + i * 256] = v[i] * inv;
}

// ---------------------------------------------------------------------------
// K4: out = x + param * (val . simT)   (M=c, N=n, K=1024)
// ---------------------------------------------------------------------------
__global__ __launch_bounds__(256) void k_attn_out(
    const float* __restrict__ x, const float* __restrict__ param,
    float* __restrict__ out) {
    extern __shared__ __align__(16) __nv_bfloat16 dsm[];
    const int b = blockIdx.z, nBase = blockIdx.x * 128, cBase = blockIdx.y * 128;
    DECL_ACC();
    const float* aSrc = g_val + ((size_t)b * C_ + cBase) * HW_;
    const float* bSrc = g_energy + ((size_t)b * HW_ + nBase) * HW_;
    gemm_core(aSrc, HW_, bSrc, HW_, 32, dsm, acc);

    if ((threadIdx.x >> 5) < 4) {
        const float ps = param[0];
        #pragma unroll
        for (int i = 0; i < 4; ++i)
            #pragma unroll
            for (int j = 0; j < 8; ++j) {
                const int c0 = cBase + EPI_M(i);
                const int ln = EPI_N(j);
                const size_t o0 = ((size_t)b * C_ + c0) * HW_ + nBase + ln;
                const size_t o1 = ((size_t)b * C_ + c0 + 8) * HW_ + nBase + ln;
                float2 x0 = *(const float2*)(x + o0);
                float2 x1 = *(const float2*)(x + o1);
                *(float2*)(out + o0) = make_float2(x0.x + ps * acc[i][j][0],
                                                   x0.y + ps * acc[i][j][1]);
                *(float2*)(out + o1) = make_float2(x1.x + ps * acc[i][j][2],
                                                   x1.y + ps * acc[i][j][3]);
            }
    }
}

// ---------------------------------------------------------------------------
// Launch
// ---------------------------------------------------------------------------
extern "C" void kernel_launch(void* const* d_in, const int* in_sizes, int n_in,
                              void* d_out, int out_size) {
    const float* x     = (const float*)d_in[0];
    const float* Wk    = (const float*)d_in[1];
    const float* bk    = (const float*)d_in[2];
    const float* Wp    = (const float*)d_in[3];
    const float* bp    = (const float*)d_in[4];
    const float* Wv    = (const float*)d_in[5];
    const float* bv    = (const float*)d_in[6];
    const float* param = (const float*)d_in[7];
    float* out = (float*)d_out;

    // Unconditional every call (no static guards; idempotent, capture-legal)
    cudaFuncSetAttribute(k_proj_kp,  cudaFuncAttributeMaxDynamicSharedMemorySize, SMEM_BYTES);
    cudaFuncSetAttribute(k_proj_v,   cudaFuncAttributeMaxDynamicSharedMemorySize, SMEM_BYTES);
    cudaFuncSetAttribute(k_energy_t, cudaFuncAttributeMaxDynamicSharedMemorySize, SMEM_BYTES);
    cudaFuncSetAttribute(k_attn_out, cudaFuncAttributeMaxDynamicSharedMemorySize, SMEM_BYTES);

    // K0: x -> xT
    k_transpose<<<dim3(HW_ / 32, C_ / 32, B_), 256>>>(x);

    // K1a: key+prod projections -> projT
    k_proj_kp<<<dim3(4, 8, B_), 256, SMEM_BYTES>>>(Wk, bk, Wp, bp);

    // K1b: value projection -> val
    k_proj_v<<<dim3(8, 4, B_), 256, SMEM_BYTES>>>(Wv, bv);

    // K2: energy
    k_energy_t<<<dim3(8, 8, B_), 256, SMEM_BYTES>>>();

    // K3: softmax in place
    k_softmax<<<B_ * HW_, 256>>>();

    // K4: attended + residual -> out
    k_attn_out<<<dim3(8, 4, B_), 256, SMEM_BYTES>>>(x, param, out);
}